// round 2
// baseline (speedup 1.0000x reference)
#include <cuda_runtime.h>
#include <cstdint>
#include <cstddef>

#define H      128
#define EMB    64
#define LAYERS 3
#define N_MAX  100000
#define E_MAX  1600000
#define G_MAX  1024

#define LDT 136                       // smem row stride (words): bank = 8*gid+tig, conflict-free
#define GEMM_SMEM (2 * 128 * LDT * 4) // 139264 bytes

// ---------------- scratch (device globals; no allocation allowed) ----------------
__device__ float g_P [(size_t)N_MAX * H];   // pre-BN activations
__device__ float g_HW[(size_t)N_MAX * H];   // GEMM output h @ Ws[l]
__device__ int   g_deg[N_MAX];
__device__ float g_dinv[N_MAX];
__device__ int   g_rowptr[N_MAX + 1];
__device__ int   g_cursor[N_MAX];
__device__ int   g_csrsrc[E_MAX];
__device__ float g_csrw[E_MAX];
__device__ int   g_chunksum[128];
__device__ int   g_chunkoff[128];
__device__ float g_bnsum[LAYERS * H];
__device__ float g_bnsq [LAYERS * H];
__device__ float g_ts[(LAYERS + 1) * H];    // per-slot BN scale (slot 0 = identity)
__device__ float g_tt[(LAYERS + 1) * H];    // per-slot BN shift
__device__ int   g_gstart[G_MAX + 1];
__device__ float g_pooled[(size_t)G_MAX * H];

// ---------------- init ----------------
__global__ void k_init(int Nn) {
    int i = blockIdx.x * blockDim.x + threadIdx.x;
    if (i < Nn) { g_deg[i] = 0; g_cursor[i] = 0; }
    if (i < H)  { g_ts[i] = 1.0f; g_tt[i] = 0.0f; }
    if (i < LAYERS * H) { g_bnsum[i] = 0.0f; g_bnsq[i] = 0.0f; }
}

// ---------------- degree count / dinv ----------------
__global__ void k_count(const int* __restrict__ ei, int E) {
    int e = blockIdx.x * blockDim.x + threadIdx.x;
    if (e < E) atomicAdd(&g_deg[ei[E + e]], 1);
}

__global__ void k_dinv(int Nn) {
    int i = blockIdx.x * blockDim.x + threadIdx.x;
    if (i < Nn) g_dinv[i] = rsqrtf((float)g_deg[i] + 1.0f);
}

// ---------------- exclusive scan (1024-elem chunks) ----------------
__global__ void k_chunksum(int Nn) {
    __shared__ int sm[256];
    int base = blockIdx.x * 1024;
    int s = 0;
    for (int j = threadIdx.x; j < 1024; j += 256) {
        int i = base + j;
        if (i < Nn) s += g_deg[i];
    }
    sm[threadIdx.x] = s; __syncthreads();
    for (int d = 128; d > 0; d >>= 1) {
        if (threadIdx.x < d) sm[threadIdx.x] += sm[threadIdx.x + d];
        __syncthreads();
    }
    if (threadIdx.x == 0) g_chunksum[blockIdx.x] = sm[0];
}

__global__ void k_scanchunks(int nb) {
    if (threadIdx.x == 0) {
        int acc = 0;
        for (int b = 0; b < nb; b++) { g_chunkoff[b] = acc; acc += g_chunksum[b]; }
    }
}

__global__ void k_scanlocal(int Nn, int E) {
    __shared__ int sm[1024];
    int i = blockIdx.x * 1024 + threadIdx.x;
    int v = (i < Nn) ? g_deg[i] : 0;
    sm[threadIdx.x] = v; __syncthreads();
    for (int d = 1; d < 1024; d <<= 1) {
        int x = (threadIdx.x >= d) ? sm[threadIdx.x - d] : 0;
        __syncthreads();
        sm[threadIdx.x] += x;
        __syncthreads();
    }
    if (i < Nn) g_rowptr[i] = g_chunkoff[blockIdx.x] + sm[threadIdx.x] - v;  // exclusive
    if (i == 0) g_rowptr[Nn] = E;
}

// ---------------- CSR scatter ----------------
__global__ void k_scatter(const int* __restrict__ ei, int E) {
    int e = blockIdx.x * blockDim.x + threadIdx.x;
    if (e >= E) return;
    int s = ei[e], d = ei[E + e];
    int pos = g_rowptr[d] + atomicAdd(&g_cursor[d], 1);
    g_csrsrc[pos] = s;
    g_csrw[pos]   = g_dinv[s] * g_dinv[d];
}

// ---------------- graph boundary (batch is sorted) ----------------
__global__ void k_gstart(const int* __restrict__ batch, int Nn, int G) {
    int g = blockIdx.x * blockDim.x + threadIdx.x;
    if (g > G) return;
    if (g == G) { g_gstart[G] = Nn; return; }
    int lo = 0, hi = Nn;
    while (lo < hi) {
        int mid = (lo + hi) >> 1;
        if (batch[mid] < g) lo = mid + 1; else hi = mid;
    }
    g_gstart[g] = lo;
}

// ---------------- tf32 helpers ----------------
__device__ __forceinline__ uint32_t f2tf32(float f) {
    uint32_t r;
    asm("cvt.rna.tf32.f32 %0, %1;" : "=r"(r) : "f"(f));
    return r;
}

// ---------------- TF32 tensor-core GEMM: C[M,128] = f(A)[M,128] @ B[128,128] (+bias) ----
// TRANSFORM=1: A element at channel k becomes relu(a*s[k]+t[k])  (fused BN+ReLU)
// Full K=128 resident in smem; 8 warps, warp tile 32x64, mma.m16n8k8.tf32.
template <int TRANSFORM>
__global__ void __launch_bounds__(256) k_gemm_mma(
    const float* __restrict__ A, const float* __restrict__ B, float* __restrict__ C,
    int M, const float* __restrict__ s, const float* __restrict__ t,
    const float* __restrict__ bias)
{
    extern __shared__ uint32_t dynsmem[];
    uint32_t* sA = dynsmem;                 // [128][LDT]  A[m][k] as tf32
    uint32_t* sB = dynsmem + 128 * LDT;     // [128][LDT]  B[k][n] as tf32

    const int tid = threadIdx.x;
    const int m0  = blockIdx.x * 128;
    const int lane_k4 = (tid & 31) * 4;     // column quadruple this thread handles

    // -------- load A tile (with fused BN+ReLU) --------
    float4 sv, tv;
    if (TRANSFORM) {
        sv = *(const float4*)(s + lane_k4);
        tv = *(const float4*)(t + lane_k4);
    }
#pragma unroll
    for (int it = 0; it < 16; it++) {
        int idx = tid + it * 256;
        int m = idx >> 5;
        int gm = m0 + m;
        float4 v = make_float4(0.f, 0.f, 0.f, 0.f);
        if (gm < M) v = *(const float4*)(A + (size_t)gm * H + lane_k4);
        if (TRANSFORM) {
            v.x = fmaxf(fmaf(v.x, sv.x, tv.x), 0.f);
            v.y = fmaxf(fmaf(v.y, sv.y, tv.y), 0.f);
            v.z = fmaxf(fmaf(v.z, sv.z, tv.z), 0.f);
            v.w = fmaxf(fmaf(v.w, sv.w, tv.w), 0.f);
        }
        uint4 r = make_uint4(f2tf32(v.x), f2tf32(v.y), f2tf32(v.z), f2tf32(v.w));
        *(uint4*)(sA + m * LDT + lane_k4) = r;
    }
    // -------- load B tile --------
#pragma unroll
    for (int it = 0; it < 16; it++) {
        int idx = tid + it * 256;
        int k = idx >> 5;
        float4 v = *(const float4*)(B + (size_t)k * H + lane_k4);
        uint4 r = make_uint4(f2tf32(v.x), f2tf32(v.y), f2tf32(v.z), f2tf32(v.w));
        *(uint4*)(sB + k * LDT + lane_k4) = r;
    }
    __syncthreads();

    // -------- mma mainloop --------
    const int lane = tid & 31;
    const int gid  = lane >> 2;   // group id 0..7
    const int tig  = lane & 3;    // thread in group 0..3
    const int wid  = tid >> 5;
    const int wm   = (wid & 3) * 32;   // warp M offset
    const int wn   = (wid >> 2) * 64;  // warp N offset

    float acc[2][8][4];
#pragma unroll
    for (int mt = 0; mt < 2; mt++)
#pragma unroll
        for (int nt = 0; nt < 8; nt++)
#pragma unroll
            for (int q = 0; q < 4; q++) acc[mt][nt][q] = 0.f;

#pragma unroll
    for (int ks = 0; ks < 16; ks++) {
        const int k0 = ks * 8 + tig;
        uint32_t a[2][4];
#pragma unroll
        for (int mt = 0; mt < 2; mt++) {
            const uint32_t* pa = sA + (wm + mt * 16 + gid) * LDT + k0;
            a[mt][0] = pa[0];
            a[mt][1] = pa[8 * LDT];
            a[mt][2] = pa[4];
            a[mt][3] = pa[8 * LDT + 4];
        }
#pragma unroll
        for (int nt = 0; nt < 8; nt++) {
            const uint32_t* pb = sB + k0 * LDT + wn + nt * 8 + gid;
            uint32_t b0 = pb[0];
            uint32_t b1 = pb[4 * LDT];
#pragma unroll
            for (int mt = 0; mt < 2; mt++) {
                asm volatile(
                    "mma.sync.aligned.m16n8k8.row.col.f32.tf32.tf32.f32 "
                    "{%0,%1,%2,%3}, {%4,%5,%6,%7}, {%8,%9}, {%0,%1,%2,%3};"
                    : "+f"(acc[mt][nt][0]), "+f"(acc[mt][nt][1]),
                      "+f"(acc[mt][nt][2]), "+f"(acc[mt][nt][3])
                    : "r"(a[mt][0]), "r"(a[mt][1]), "r"(a[mt][2]), "r"(a[mt][3]),
                      "r"(b0), "r"(b1));
            }
        }
    }

    // -------- epilogue --------
#pragma unroll
    for (int mt = 0; mt < 2; mt++) {
#pragma unroll
        for (int nt = 0; nt < 8; nt++) {
            int r0 = m0 + wm + mt * 16 + gid;
            int c  = wn + nt * 8 + tig * 2;
            float2 v0 = make_float2(acc[mt][nt][0], acc[mt][nt][1]);
            float2 v1 = make_float2(acc[mt][nt][2], acc[mt][nt][3]);
            if (!TRANSFORM && bias) {
                float b0 = bias[c], b1 = bias[c + 1];
                v0.x += b0; v0.y += b1;
                v1.x += b0; v1.y += b1;
            }
            if (r0 < M)     *(float2*)(C + (size_t)r0 * H + c)       = v0;
            if (r0 + 8 < M) *(float2*)(C + (size_t)(r0 + 8) * H + c) = v1;
        }
    }
}

// ---------------- edge aggregation: warp per dst node (no atomics) ----------------
__global__ void k_agg(const float* __restrict__ HWp, const float* __restrict__ bias,
                      float* __restrict__ OUT, int Nn)
{
    int w    = (blockIdx.x * blockDim.x + threadIdx.x) >> 5;
    int lane = threadIdx.x & 31;
    if (w >= Nn) return;
    const float4* hw4 = (const float4*)HWp;
    int e0 = g_rowptr[w], e1 = g_rowptr[w + 1];
    float4 acc = make_float4(0.f, 0.f, 0.f, 0.f);
    for (int e = e0; e < e1; e++) {
        int   src = g_csrsrc[e];
        float wt  = g_csrw[e];
        float4 v = hw4[(size_t)src * 32 + lane];
        acc.x = fmaf(wt, v.x, acc.x);
        acc.y = fmaf(wt, v.y, acc.y);
        acc.z = fmaf(wt, v.z, acc.z);
        acc.w = fmaf(wt, v.w, acc.w);
    }
    float di = g_dinv[w];
    float sn = di * di;                       // 1/deg (self-loop norm)
    float4 sv = hw4[(size_t)w * 32 + lane];
    acc.x = fmaf(sn, sv.x, acc.x) + bias[lane * 4 + 0];
    acc.y = fmaf(sn, sv.y, acc.y) + bias[lane * 4 + 1];
    acc.z = fmaf(sn, sv.z, acc.z) + bias[lane * 4 + 2];
    acc.w = fmaf(sn, sv.w, acc.w) + bias[lane * 4 + 3];
    ((float4*)OUT)[(size_t)w * 32 + lane] = acc;
}

// ---------------- BatchNorm statistics & finalize ----------------
__global__ void k_bnstats(const float* __restrict__ P, int Nn, int layer) {
    int c = threadIdx.x;  // 128 threads
    float s = 0.f, q = 0.f;
    for (int r = blockIdx.x; r < Nn; r += gridDim.x) {
        float v = P[(size_t)r * H + c];
        s += v;
        q = fmaf(v, v, q);
    }
    atomicAdd(&g_bnsum[layer * H + c], s);
    atomicAdd(&g_bnsq [layer * H + c], q);
}

__global__ void k_bnfin(const float* __restrict__ gammas, const float* __restrict__ betas,
                        int Nn, int layer) {
    int c = threadIdx.x;
    float invN = 1.0f / (float)Nn;
    float mean = g_bnsum[layer * H + c] * invN;
    float var  = g_bnsq [layer * H + c] * invN - mean * mean;
    float inv  = rsqrtf(var + 1e-5f);
    float sc   = gammas[layer * H + c] * inv;
    g_ts[(layer + 1) * H + c] = sc;
    g_tt[(layer + 1) * H + c] = betas[layer * H + c] - mean * sc;
}

// ---------------- global mean pool (block per graph; applies layer-3 BN+ReLU) ----------------
__global__ void k_pool(const float* __restrict__ P) {
    int g = blockIdx.x, c = threadIdx.x;
    int a = g_gstart[g], b = g_gstart[g + 1];
    float sc = g_ts[LAYERS * H + c], tt = g_tt[LAYERS * H + c];
    float acc = 0.f;
    for (int r = a; r < b; r++)
        acc += fmaxf(fmaf(P[(size_t)r * H + c], sc, tt), 0.f);
    g_pooled[(size_t)g * H + c] = acc / fmaxf((float)(b - a), 1.0f);
}

// ---------------- head MLP: out = relu(pooled@W1+b1)@W2+b2 ----------------
__global__ void k_mlp(const float* __restrict__ W1, const float* __restrict__ b1,
                      const float* __restrict__ W2, const float* __restrict__ b2,
                      float* __restrict__ out) {
    __shared__ float p[H], t1[H];
    int g = blockIdx.x, c = threadIdx.x;
    p[c] = g_pooled[(size_t)g * H + c];
    __syncthreads();
    float acc = b1[c];
#pragma unroll
    for (int k = 0; k < H; k++) acc = fmaf(p[k], W1[k * H + c], acc);
    t1[c] = fmaxf(acc, 0.f);
    __syncthreads();
    if (c < EMB) {
        float o = b2[c];
#pragma unroll
        for (int k = 0; k < H; k++) o = fmaf(t1[k], W2[k * EMB + c], o);
        out[(size_t)g * EMB + c] = o;
    }
}

// ---------------- launch ----------------
extern "C" void kernel_launch(void* const* d_in, const int* in_sizes, int n_in,
                              void* d_out, int out_size)
{
    const float* x      = (const float*)d_in[0];
    const int*   ei     = (const int*)  d_in[1];
    const int*   batch  = (const int*)  d_in[2];
    const float* W_in   = (const float*)d_in[3];
    const float* b_in   = (const float*)d_in[4];
    const float* Ws     = (const float*)d_in[5];
    const float* bs     = (const float*)d_in[6];
    const float* gammas = (const float*)d_in[7];
    const float* betas  = (const float*)d_in[8];
    const float* W1     = (const float*)d_in[9];
    const float* b1     = (const float*)d_in[10];
    const float* W2     = (const float*)d_in[11];
    const float* b2     = (const float*)d_in[12];

    int Nn = in_sizes[0] / H;
    int E  = in_sizes[1] / 2;
    int G  = out_size / EMB;

    float *P, *HWp, *ts, *tt;
    cudaGetSymbolAddress((void**)&P,   g_P);
    cudaGetSymbolAddress((void**)&HWp, g_HW);
    cudaGetSymbolAddress((void**)&ts,  g_ts);
    cudaGetSymbolAddress((void**)&tt,  g_tt);

    cudaFuncSetAttribute(k_gemm_mma<0>, cudaFuncAttributeMaxDynamicSharedMemorySize, GEMM_SMEM);
    cudaFuncSetAttribute(k_gemm_mma<1>, cudaFuncAttributeMaxDynamicSharedMemorySize, GEMM_SMEM);

    // graph structure (recomputed every launch; deterministic)
    k_init<<<(Nn + 255) / 256, 256>>>(Nn);
    k_count<<<(E + 255) / 256, 256>>>(ei, E);
    k_dinv<<<(Nn + 255) / 256, 256>>>(Nn);
    int nb = (Nn + 1023) / 1024;
    k_chunksum<<<nb, 256>>>(Nn);
    k_scanchunks<<<1, 32>>>(nb);
    k_scanlocal<<<nb, 1024>>>(Nn, E);
    k_scatter<<<(E + 255) / 256, 256>>>(ei, E);
    k_gstart<<<(G + 256) / 256, 256>>>(batch, Nn, G);

    int mblocks = (Nn + 127) / 128;

    // input projection: P = x@W_in + b_in  (ReLU deferred to slot-0 identity transform)
    k_gemm_mma<0><<<mblocks, 256, GEMM_SMEM>>>(x, W_in, P, Nn, nullptr, nullptr, b_in);

    for (int l = 0; l < LAYERS; l++) {
        // HW = relu(bn(P)) @ Ws[l]   (BN+ReLU fused into A-tile load; slot0 = identity)
        k_gemm_mma<1><<<mblocks, 256, GEMM_SMEM>>>(P, Ws + l * H * H, HWp, Nn,
                                                   ts + l * H, tt + l * H, nullptr);
        // P = agg(HW) + HW*self_norm + bs[l]   (pre-BN)
        k_agg<<<(Nn * 32 + 255) / 256, 256>>>(HWp, bs + l * H, P, Nn);
        k_bnstats<<<296, 128>>>(P, Nn, l);
        k_bnfin<<<1, 128>>>(gammas, betas, Nn, l);
    }

    k_pool<<<G, 128>>>(P);
    k_mlp<<<G, 128>>>(W1, b1, W2, b2, (float*)d_out);
}

// round 4
// speedup vs baseline: 1.0982x; 1.0982x over previous
#include <cuda_runtime.h>
#include <cstdint>
#include <cstddef>

#define H      128
#define EMB    64
#define LAYERS 3
#define N_MAX  100000
#define E_MAX  1600000
#define G_MAX  1024

// ---------------- scratch (device globals; no allocation allowed) ----------------
__device__ float g_P [(size_t)N_MAX * H];   // pre-BN activations
__device__ float g_HW[(size_t)N_MAX * H];   // GEMM output h @ Ws[l]
__device__ int   g_deg[N_MAX];
__device__ float g_dinv[N_MAX];
__device__ int   g_rowptr[N_MAX + 1];
__device__ int   g_cursor[N_MAX];
__device__ int   g_csrsrc[E_MAX];
__device__ float g_csrw[E_MAX];
__device__ int   g_chunksum[128];
__device__ int   g_chunkoff[128];
__device__ float g_bnsum[LAYERS * H];
__device__ float g_bnsq [LAYERS * H];
__device__ float g_ts[(LAYERS + 1) * H];    // per-slot BN scale (slot 0 = identity)
__device__ float g_tt[(LAYERS + 1) * H];    // per-slot BN shift
__device__ int   g_gstart[G_MAX + 1];
__device__ float g_pooled[(size_t)G_MAX * H];

// ---------------- init ----------------
__global__ void k_init(int Nn) {
    int i = blockIdx.x * blockDim.x + threadIdx.x;
    if (i < Nn) { g_deg[i] = 0; g_cursor[i] = 0; }
    if (i < H)  { g_ts[i] = 1.0f; g_tt[i] = 0.0f; }
    if (i < LAYERS * H) { g_bnsum[i] = 0.0f; g_bnsq[i] = 0.0f; }
}

// ---------------- degree count / dinv ----------------
__global__ void k_count(const int* __restrict__ ei, int E) {
    int e = blockIdx.x * blockDim.x + threadIdx.x;
    if (e < E) atomicAdd(&g_deg[ei[E + e]], 1);
}

__global__ void k_dinv(int Nn) {
    int i = blockIdx.x * blockDim.x + threadIdx.x;
    if (i < Nn) g_dinv[i] = rsqrtf((float)g_deg[i] + 1.0f);
}

// ---------------- exclusive scan (1024-elem chunks) ----------------
__global__ void k_chunksum(int Nn) {
    __shared__ int sm[256];
    int base = blockIdx.x * 1024;
    int s = 0;
    for (int j = threadIdx.x; j < 1024; j += 256) {
        int i = base + j;
        if (i < Nn) s += g_deg[i];
    }
    sm[threadIdx.x] = s; __syncthreads();
    for (int d = 128; d > 0; d >>= 1) {
        if (threadIdx.x < d) sm[threadIdx.x] += sm[threadIdx.x + d];
        __syncthreads();
    }
    if (threadIdx.x == 0) g_chunksum[blockIdx.x] = sm[0];
}

__global__ void k_scanchunks(int nb) {
    if (threadIdx.x == 0) {
        int acc = 0;
        for (int b = 0; b < nb; b++) { g_chunkoff[b] = acc; acc += g_chunksum[b]; }
    }
}

__global__ void k_scanlocal(int Nn, int E) {
    __shared__ int sm[1024];
    int i = blockIdx.x * 1024 + threadIdx.x;
    int v = (i < Nn) ? g_deg[i] : 0;
    sm[threadIdx.x] = v; __syncthreads();
    for (int d = 1; d < 1024; d <<= 1) {
        int x = (threadIdx.x >= d) ? sm[threadIdx.x - d] : 0;
        __syncthreads();
        sm[threadIdx.x] += x;
        __syncthreads();
    }
    if (i < Nn) g_rowptr[i] = g_chunkoff[blockIdx.x] + sm[threadIdx.x] - v;  // exclusive
    if (i == 0) g_rowptr[Nn] = E;
}

// ---------------- CSR scatter ----------------
__global__ void k_scatter(const int* __restrict__ ei, int E) {
    int e = blockIdx.x * blockDim.x + threadIdx.x;
    if (e >= E) return;
    int s = ei[e], d = ei[E + e];
    int pos = g_rowptr[d] + atomicAdd(&g_cursor[d], 1);
    g_csrsrc[pos] = s;
    g_csrw[pos]   = g_dinv[s] * g_dinv[d];
}

// ---------------- graph boundary (batch is sorted) ----------------
__global__ void k_gstart(const int* __restrict__ batch, int Nn, int G) {
    int g = blockIdx.x * blockDim.x + threadIdx.x;
    if (g > G) return;
    if (g == G) { g_gstart[G] = Nn; return; }
    int lo = 0, hi = Nn;
    while (lo < hi) {
        int mid = (lo + hi) >> 1;
        if (batch[mid] < g) lo = mid + 1; else hi = mid;
    }
    g_gstart[g] = lo;
}

// ---------------- packed f32x2 helpers (Blackwell base-family) ----------------
__device__ __forceinline__ void fma_f32x2(unsigned long long& acc,
                                          unsigned long long a,
                                          unsigned long long b) {
    asm("fma.rn.f32x2 %0, %1, %2, %0;" : "+l"(acc) : "l"(a), "l"(b));
}
__device__ __forceinline__ unsigned long long dup_f32(float v) {
    unsigned long long r;
    asm("mov.b64 %0, {%1, %1};" : "=l"(r) : "f"(v));
    return r;
}

// ---------------- SGEMM (FFMA2): C[M,128] = f(A)[M,128] @ B[128,128] (+bias) ------
// TRANSFORM=1: A element at channel k becomes relu(a*s[k]+t[k])  (fused BN+ReLU)
// Accumulators packed pairwise along M: acc2[i2][j] = {C[m+2i2][n+j], C[m+2i2+1][n+j]}
template <int TRANSFORM>
__global__ void __launch_bounds__(256, 2) k_gemm(
    const float* __restrict__ A, const float* __restrict__ B, float* __restrict__ C,
    int M, const float* __restrict__ s, const float* __restrict__ t,
    const float* __restrict__ bias)
{
    __shared__ float As[16][132];   // [k][m], padded; m contiguous (needed for pair loads)
    __shared__ float Bs[16][128];   // [k][n]
    const int tid = threadIdx.x;
    const int tx = tid & 15, ty = tid >> 4;
    const int m0 = blockIdx.x * 128;

    unsigned long long acc2[4][8];
#pragma unroll
    for (int i = 0; i < 4; i++)
#pragma unroll
        for (int j = 0; j < 8; j++) acc2[i][j] = 0ULL;

    for (int kt = 0; kt < H; kt += 16) {
#pragma unroll
        for (int l = 0; l < 2; l++) {
            int idx = tid + l * 256;
            int row = idx >> 2, c4 = (idx & 3) * 4;
            int gm = m0 + row;
            float4 v = make_float4(0.f, 0.f, 0.f, 0.f);
            if (gm < M) v = *(const float4*)(A + (size_t)gm * H + kt + c4);
            if (TRANSFORM) {
                int kg = kt + c4;
                v.x = fmaxf(fmaf(v.x, s[kg],     t[kg]),     0.f);
                v.y = fmaxf(fmaf(v.y, s[kg + 1], t[kg + 1]), 0.f);
                v.z = fmaxf(fmaf(v.z, s[kg + 2], t[kg + 2]), 0.f);
                v.w = fmaxf(fmaf(v.w, s[kg + 3], t[kg + 3]), 0.f);
            }
            As[c4 + 0][row] = v.x; As[c4 + 1][row] = v.y;
            As[c4 + 2][row] = v.z; As[c4 + 3][row] = v.w;
        }
#pragma unroll
        for (int l = 0; l < 2; l++) {
            int idx = tid + l * 256;
            int row = idx >> 5, cc = (idx & 31) * 4;
            *(float4*)(&Bs[row][cc]) = *(const float4*)(B + (size_t)(kt + row) * H + cc);
        }
        __syncthreads();
#pragma unroll
        for (int k = 0; k < 16; k++) {
            // a pairs: m-contiguous in As -> direct 64-bit pair loads
            unsigned long long a2[4];
            const ulonglong2 ap0 = *(const ulonglong2*)(&As[k][ty * 8]);
            const ulonglong2 ap1 = *(const ulonglong2*)(&As[k][ty * 8 + 4]);
            a2[0] = ap0.x; a2[1] = ap0.y; a2[2] = ap1.x; a2[3] = ap1.y;
            // b scalars -> duplicated pairs
            float b[8];
            *(float4*)(b)     = *(const float4*)(&Bs[k][tx * 8]);
            *(float4*)(b + 4) = *(const float4*)(&Bs[k][tx * 8 + 4]);
            unsigned long long bd[8];
#pragma unroll
            for (int j = 0; j < 8; j++) bd[j] = dup_f32(b[j]);
#pragma unroll
            for (int i = 0; i < 4; i++)
#pragma unroll
                for (int j = 0; j < 8; j++)
                    fma_f32x2(acc2[i][j], a2[i], bd[j]);
        }
        __syncthreads();
    }

    // epilogue: acc2[i2][j] = rows (ty*8+2*i2, +1), col tx*8+j
#pragma unroll
    for (int i2 = 0; i2 < 4; i2++) {
        int gm = m0 + ty * 8 + 2 * i2;
        float lo[8], hi[8];
#pragma unroll
        for (int j = 0; j < 8; j++) {
            float2 p = *(float2*)(&acc2[i2][j]);
            lo[j] = p.x; hi[j] = p.y;
        }
        if (bias) {
#pragma unroll
            for (int j = 0; j < 8; j++) {
                float bj = bias[tx * 8 + j];
                lo[j] += bj; hi[j] += bj;
            }
        }
        if (gm < M) {
            *(float4*)(C + (size_t)gm * H + tx * 8)     = *(float4*)(lo);
            *(float4*)(C + (size_t)gm * H + tx * 8 + 4) = *(float4*)(lo + 4);
        }
        if (gm + 1 < M) {
            *(float4*)(C + (size_t)(gm + 1) * H + tx * 8)     = *(float4*)(hi);
            *(float4*)(C + (size_t)(gm + 1) * H + tx * 8 + 4) = *(float4*)(hi + 4);
        }
    }
}

// ---------------- edge aggregation: warp per dst node (no atomics) ----------------
__global__ void k_agg(const float* __restrict__ HWp, const float* __restrict__ bias,
                      float* __restrict__ OUT, int Nn)
{
    int w    = (blockIdx.x * blockDim.x + threadIdx.x) >> 5;
    int lane = threadIdx.x & 31;
    if (w >= Nn) return;
    const float4* hw4 = (const float4*)HWp;
    int e0 = g_rowptr[w], e1 = g_rowptr[w + 1];
    float4 acc = make_float4(0.f, 0.f, 0.f, 0.f);
    for (int e = e0; e < e1; e++) {
        int   src = g_csrsrc[e];
        float wt  = g_csrw[e];
        float4 v = hw4[(size_t)src * 32 + lane];
        acc.x = fmaf(wt, v.x, acc.x);
        acc.y = fmaf(wt, v.y, acc.y);
        acc.z = fmaf(wt, v.z, acc.z);
        acc.w = fmaf(wt, v.w, acc.w);
    }
    float di = g_dinv[w];
    float sn = di * di;                       // 1/deg (self-loop norm)
    float4 sv = hw4[(size_t)w * 32 + lane];
    acc.x = fmaf(sn, sv.x, acc.x) + bias[lane * 4 + 0];
    acc.y = fmaf(sn, sv.y, acc.y) + bias[lane * 4 + 1];
    acc.z = fmaf(sn, sv.z, acc.z) + bias[lane * 4 + 2];
    acc.w = fmaf(sn, sv.w, acc.w) + bias[lane * 4 + 3];
    ((float4*)OUT)[(size_t)w * 32 + lane] = acc;
}

// ---------------- BatchNorm statistics & finalize ----------------
__global__ void k_bnstats(const float* __restrict__ P, int Nn, int layer) {
    int c = threadIdx.x;  // 128 threads
    float s = 0.f, q = 0.f;
    for (int r = blockIdx.x; r < Nn; r += gridDim.x) {
        float v = P[(size_t)r * H + c];
        s += v;
        q = fmaf(v, v, q);
    }
    atomicAdd(&g_bnsum[layer * H + c], s);
    atomicAdd(&g_bnsq [layer * H + c], q);
}

__global__ void k_bnfin(const float* __restrict__ gammas, const float* __restrict__ betas,
                        int Nn, int layer) {
    int c = threadIdx.x;
    float invN = 1.0f / (float)Nn;
    float mean = g_bnsum[layer * H + c] * invN;
    float var  = g_bnsq [layer * H + c] * invN - mean * mean;
    float inv  = rsqrtf(var + 1e-5f);
    float sc   = gammas[layer * H + c] * inv;
    g_ts[(layer + 1) * H + c] = sc;
    g_tt[(layer + 1) * H + c] = betas[layer * H + c] - mean * sc;
}

// ---------------- global mean pool (block per graph; applies layer-3 BN+ReLU) ----------------
__global__ void k_pool(const float* __restrict__ P) {
    int g = blockIdx.x, c = threadIdx.x;
    int a = g_gstart[g], b = g_gstart[g + 1];
    float sc = g_ts[LAYERS * H + c], tt = g_tt[LAYERS * H + c];
    float acc = 0.f;
    for (int r = a; r < b; r++)
        acc += fmaxf(fmaf(P[(size_t)r * H + c], sc, tt), 0.f);
    g_pooled[(size_t)g * H + c] = acc / fmaxf((float)(b - a), 1.0f);
}

// ---------------- head MLP: out = relu(pooled@W1+b1)@W2+b2 ----------------
__global__ void k_mlp(const float* __restrict__ W1, const float* __restrict__ b1,
                      const float* __restrict__ W2, const float* __restrict__ b2,
                      float* __restrict__ out) {
    __shared__ float p[H], t1[H];
    int g = blockIdx.x, c = threadIdx.x;
    p[c] = g_pooled[(size_t)g * H + c];
    __syncthreads();
    float acc = b1[c];
#pragma unroll
    for (int k = 0; k < H; k++) acc = fmaf(p[k], W1[k * H + c], acc);
    t1[c] = fmaxf(acc, 0.f);
    __syncthreads();
    if (c < EMB) {
        float o = b2[c];
#pragma unroll
        for (int k = 0; k < H; k++) o = fmaf(t1[k], W2[k * EMB + c], o);
        out[(size_t)g * EMB + c] = o;
    }
}

// ---------------- launch ----------------
extern "C" void kernel_launch(void* const* d_in, const int* in_sizes, int n_in,
                              void* d_out, int out_size)
{
    const float* x      = (const float*)d_in[0];
    const int*   ei     = (const int*)  d_in[1];
    const int*   batch  = (const int*)  d_in[2];
    const float* W_in   = (const float*)d_in[3];
    const float* b_in   = (const float*)d_in[4];
    const float* Ws     = (const float*)d_in[5];
    const float* bs     = (const float*)d_in[6];
    const float* gammas = (const float*)d_in[7];
    const float* betas  = (const float*)d_in[8];
    const float* W1     = (const float*)d_in[9];
    const float* b1     = (const float*)d_in[10];
    const float* W2     = (const float*)d_in[11];
    const float* b2     = (const float*)d_in[12];

    int Nn = in_sizes[0] / H;
    int E  = in_sizes[1] / 2;
    int G  = out_size / EMB;

    float *P, *HWp, *ts, *tt;
    cudaGetSymbolAddress((void**)&P,   g_P);
    cudaGetSymbolAddress((void**)&HWp, g_HW);
    cudaGetSymbolAddress((void**)&ts,  g_ts);
    cudaGetSymbolAddress((void**)&tt,  g_tt);

    int mblocks = (Nn + 127) / 128;
    int nb = (Nn + 1023) / 1024;

    // input projection early (also lands GEMMs near the ncu -s window)
    k_init<<<(Nn + 255) / 256, 256>>>(Nn);
    k_gemm<0><<<mblocks, 256>>>(x, W_in, P, Nn, nullptr, nullptr, b_in);
    k_gemm<1><<<mblocks, 256>>>(P, Ws, HWp, Nn, ts, tt, nullptr);

    // graph structure (recomputed every launch; deterministic)
    k_count<<<(E + 255) / 256, 256>>>(ei, E);
    k_dinv<<<(Nn + 255) / 256, 256>>>(Nn);
    k_chunksum<<<nb, 256>>>(Nn);
    k_scanchunks<<<1, 32>>>(nb);
    k_scanlocal<<<nb, 1024>>>(Nn, E);
    k_scatter<<<(E + 255) / 256, 256>>>(ei, E);
    k_gstart<<<(G + 256) / 256, 256>>>(batch, Nn, G);

    for (int l = 0; l < LAYERS; l++) {
        if (l > 0)
            k_gemm<1><<<mblocks, 256>>>(P, Ws + l * H * H, HWp, Nn,
                                        ts + l * H, tt + l * H, nullptr);
        k_agg<<<(Nn * 32 + 255) / 256, 256>>>(HWp, bs + l * H, P, Nn);
        k_bnstats<<<296, 128>>>(P, Nn, l);
        k_bnfin<<<1, 128>>>(gammas, betas, Nn, l);
    }

    k_pool<<<G, 128>>>(P);
    k_mlp<<<G, 128>>>(W1, b1, W2, b2, (float*)d_out);
}